// round 17
// baseline (speedup 1.0000x reference)
#include <cuda_runtime.h>
#include <cstdint>

// B=8, N=1024, C=768, H=12, D=64.
//
// Mathematical collapse: V = spe_agg broadcast over the sequence axis is
// independent of the attention key index m, so Σ_m softmax(...)·v = v
// (softmax rows sum to exactly 1). The whole module reduces to
//   out[b, n, j] = Σ_c spe_agg[b,c] * W_proj[j,c] + b_proj[j]   (constant in n)
// x and W_qkv are mathematically unused.
//
// Evidence ledger:
//  * 25.2 MB store stream floors at ~8.2 us regardless of mechanism.
//  * One clean wave (128 blocks) beats 1.3 waves (192 blocks).
//  * R11/R14/R16 all compiled to regs=48: __launch_bounds__(384) without
//    minBlocksPerSM lets ptxas cap regs for 3-CTA occupancy we never use,
//    serializing/spilling any batched W loads. This round: launch_bounds
//    (384, 1) -> 168-reg ceiling, full 4-row batch (30 live float4) so
//    phase-1 is ONE DRAM round-trip.

#define Bk 8
#define Ck 768
#define Nk 1024
#define JS 48                 // j-columns per block (12 float4)
#define JS4 (JS / 4)          // 12
#define NJ (Ck / JS)          // 16 j-slices -> grid (16,8)=128 blocks, 1 wave
#define TPB 384               // 12 warps

__global__ void __launch_bounds__(TPB, 1) fused_kernel(
    const float* __restrict__ spe_agg,   // (B, C)
    const float* __restrict__ W_proj,    // (C, C) row-major
    const float* __restrict__ b_proj,    // (C,)
    float* __restrict__ out)             // (B, N, C)
{
    __shared__ __align__(16) float y_s[JS];

    const int b     = blockIdx.y;        // 0..7
    const int jbase = blockIdx.x * JS;   // 0,48,...,720
    const int tid   = threadIdx.x;
    const int warp  = tid >> 5;          // 0..11
    const int lane  = tid & 31;

    // ---- Phase 1: y[b][jbase..jbase+47]; each warp computes 4 j's with
    //      ALL 24 W float4 + 6 spe_agg float4 issued before any use:
    //      one DRAM latency exposure instead of four. -----------------------
    const float4* __restrict__ srow =
        reinterpret_cast<const float4*>(spe_agg + (size_t)b * Ck);
    const int j0 = jbase + warp * 4;

    float4 sreg[6];
    #pragma unroll
    for (int i = 0; i < 6; ++i) sreg[i] = srow[i * 32 + lane];

    float4 w[4][6];
    #pragma unroll
    for (int jj = 0; jj < 4; ++jj) {
        const float4* __restrict__ Wrow =
            reinterpret_cast<const float4*>(W_proj + (size_t)(j0 + jj) * Ck);
        #pragma unroll
        for (int i = 0; i < 6; ++i) w[jj][i] = Wrow[i * 32 + lane];
    }

    float acc[4] = {0.f, 0.f, 0.f, 0.f};
    #pragma unroll
    for (int jj = 0; jj < 4; ++jj)
        #pragma unroll
        for (int i = 0; i < 6; ++i)
            acc[jj] += w[jj][i].x * sreg[i].x + w[jj][i].y * sreg[i].y
                     + w[jj][i].z * sreg[i].z + w[jj][i].w * sreg[i].w;

    // 4 independent butterfly reductions — shfl latencies overlap.
    #pragma unroll
    for (int off = 16; off > 0; off >>= 1)
        #pragma unroll
        for (int jj = 0; jj < 4; ++jj)
            acc[jj] += __shfl_xor_sync(0xffffffffu, acc[jj], off);

    if (lane < 4)
        y_s[warp * 4 + lane] = acc[lane] + __ldg(&b_proj[j0 + lane]);
    __syncthreads();

    // ---- Phase 2: broadcast the 48-float slice over all 1024 n-rows ------
    // (byte-identical to the R11 champion store loop)
    const int f  = tid % JS4;            // 0..11
    const int r0 = tid / JS4;            // 0..31
    const float4 val = reinterpret_cast<const float4*>(y_s)[f];

    float* obase = out + (size_t)b * Nk * Ck + jbase;
    #pragma unroll
    for (int it = 0; it < Nk / (TPB / JS4); ++it) {      // 32 iterations
        const int r = r0 + it * (TPB / JS4);
        reinterpret_cast<float4*>(obase + (size_t)r * Ck)[f] = val;
    }
}

extern "C" void kernel_launch(void* const* d_in, const int* in_sizes, int n_in,
                              void* d_out, int out_size)
{
    // metadata order: x, spe_agg, W_qkv, W_proj, b_proj
    const float* spe_agg = (const float*)d_in[1];
    const float* W_proj  = (const float*)d_in[3];
    const float* b_proj  = (const float*)d_in[4];
    float* out           = (float*)d_out;

    (void)in_sizes; (void)n_in; (void)out_size;

    dim3 grid(NJ, Bk);                    // (16, 8) = 128 blocks — one wave
    fused_kernel<<<grid, TPB>>>(spe_agg, W_proj, b_proj, out);
}